// round 4
// baseline (speedup 1.0000x reference)
#include <cuda_runtime.h>
#include <cmath>

// Problem constants (fixed by the reference)
#define D_MODEL   1024
#define NUM_HEADS 16
#define HEAD_DIM  64
#define B_SZ      2
#define SEQ       2048
#define M_TOT     (B_SZ * SEQ)   // 4096 rows for all projection GEMMs

// Scratch (allocation-free rule: __device__ globals). 4 x 16 MB = 64 MB.
__device__ float g_Q[(size_t)M_TOT * D_MODEL];
__device__ float g_K[(size_t)M_TOT * D_MODEL];
__device__ float g_V[(size_t)M_TOT * D_MODEL];
__device__ float g_C[(size_t)M_TOT * D_MODEL];

// ---------------------------------------------------------------------------
// GEMM + bias:  Y[M,N] = X[M,K] @ W[K,N] + b[N]
// 128x128 CTA tile, BK=8, 256 threads, 8x8 per-thread micro-tile.
// ---------------------------------------------------------------------------
__global__ __launch_bounds__(256) void gemm_bias_kernel(
    const float* __restrict__ X, const float* __restrict__ W,
    const float* __restrict__ bias, float* __restrict__ Y,
    int M, int N, int K)
{
    __shared__ __align__(16) float As[8][128];   // As[k][m]
    __shared__ __align__(16) float Bs[8][128];   // Bs[k][n]

    const int tid = threadIdx.x;
    const int tx  = tid & 15;      // 0..15 -> n sub-block
    const int ty  = tid >> 4;      // 0..15 -> m sub-block
    const int m0  = blockIdx.y * 128;
    const int n0  = blockIdx.x * 128;

    float acc[8][8];
    #pragma unroll
    for (int i = 0; i < 8; i++)
        #pragma unroll
        for (int j = 0; j < 8; j++) acc[i][j] = 0.f;

    // A-load mapping: thread -> (row, 4-wide k chunk)
    const int a_m  = tid >> 1;           // 0..127
    const int a_kq = (tid & 1) * 4;      // 0 or 4
    // B-load mapping: thread -> (k row, 4-wide n chunk)
    const int b_kk = tid >> 5;           // 0..7
    const int b_n  = (tid & 31) * 4;     // 0..124

    const float* Xp = X + (size_t)(m0 + a_m) * K + a_kq;
    const float* Wp = W + (size_t)b_kk * N + n0 + b_n;

    for (int k0 = 0; k0 < K; k0 += 8) {
        float4 av = *(const float4*)(Xp + k0);
        As[a_kq + 0][a_m] = av.x;
        As[a_kq + 1][a_m] = av.y;
        As[a_kq + 2][a_m] = av.z;
        As[a_kq + 3][a_m] = av.w;
        *(float4*)&Bs[b_kk][b_n] = *(const float4*)(Wp + (size_t)k0 * N);
        __syncthreads();

        #pragma unroll
        for (int kk = 0; kk < 8; kk++) {
            float a[8], b[8];
            *(float4*)(a)     = *(const float4*)&As[kk][ty * 8];
            *(float4*)(a + 4) = *(const float4*)&As[kk][ty * 8 + 4];
            *(float4*)(b)     = *(const float4*)&Bs[kk][tx * 8];
            *(float4*)(b + 4) = *(const float4*)&Bs[kk][tx * 8 + 4];
            #pragma unroll
            for (int i = 0; i < 8; i++)
                #pragma unroll
                for (int j = 0; j < 8; j++)
                    acc[i][j] = fmaf(a[i], b[j], acc[i][j]);
        }
        __syncthreads();
    }

    #pragma unroll
    for (int i = 0; i < 8; i++) {
        const int m = m0 + ty * 8 + i;
        #pragma unroll
        for (int j = 0; j < 8; j += 4) {
            const int n = n0 + tx * 8 + j;
            float4 o;
            o.x = acc[i][j + 0] + bias[n + 0];
            o.y = acc[i][j + 1] + bias[n + 1];
            o.z = acc[i][j + 2] + bias[n + 2];
            o.w = acc[i][j + 3] + bias[n + 3];
            *(float4*)(Y + (size_t)m * N + n) = o;
        }
    }
}

// ---------------------------------------------------------------------------
// Flash attention (fp32). One CTA = one (batch, head, 64-row Q tile).
// Layouts: Q/K/V/O are [B, S, D_MODEL]; head h occupies cols [h*64, h*64+64).
// 256 threads; thread (tx,ty) owns score rows ty*4..+3, score cols tx*4..+3,
// and output dims tx*4..+3. Row reductions via shfl across the 16 tx lanes.
// ---------------------------------------------------------------------------
#define SPAD 65   // smem row pitch (floats)

__global__ __launch_bounds__(256) void attn_kernel(
    const float* __restrict__ Q, const float* __restrict__ K,
    const float* __restrict__ V, float* __restrict__ O)
{
    extern __shared__ float sm[];
    float* Qs = sm;                 // [64][SPAD]
    float* Ks = Qs + 64 * SPAD;
    float* Vs = Ks + 64 * SPAD;
    float* Ps = Vs + 64 * SPAD;

    const int tid = threadIdx.x;
    const int tx  = tid & 15;
    const int ty  = tid >> 4;
    const int qt  = blockIdx.x;   // 0..31
    const int h   = blockIdx.y;   // 0..15
    const int b   = blockIdx.z;   // 0..1
    const int q0  = qt * 64;
    const size_t base = (size_t)b * SEQ * D_MODEL + (size_t)h * HEAD_DIM;

    // Load Q tile (64 rows x 64 dims) once.
    #pragma unroll
    for (int i = 0; i < 4; i++) {
        const int idx = i * 256 + tid;      // 0..1023 float4 slots
        const int r   = idx >> 4;           // 0..63
        const int dq  = (idx & 15) * 4;     // 0..60
        float4 v = *(const float4*)(Q + base + (size_t)(q0 + r) * D_MODEL + dq);
        Qs[r * SPAD + dq + 0] = v.x;
        Qs[r * SPAD + dq + 1] = v.y;
        Qs[r * SPAD + dq + 2] = v.z;
        Qs[r * SPAD + dq + 3] = v.w;
    }

    float m_i[4], l_i[4], o[4][4];
    #pragma unroll
    for (int i = 0; i < 4; i++) {
        m_i[i] = -1e30f;
        l_i[i] = 0.f;
        #pragma unroll
        for (int j = 0; j < 4; j++) o[i][j] = 0.f;
    }

    const int r0 = ty * 4;           // score rows
    const int c0 = tx * 4;           // score cols (and output dims)
    const float scale = 0.125f;      // 1/sqrt(HEAD_DIM)

    for (int kt = 0; kt < SEQ / 64; kt++) {
        __syncthreads();   // prior-iteration readers done (also covers Qs on iter 0)

        // Load K and V tiles (64 x 64 each)
        #pragma unroll
        for (int i = 0; i < 4; i++) {
            const int idx = i * 256 + tid;
            const int r   = idx >> 4;
            const int dq  = (idx & 15) * 4;
            const size_t g = base + (size_t)(kt * 64 + r) * D_MODEL + dq;
            float4 kv = *(const float4*)(K + g);
            Ks[r * SPAD + dq + 0] = kv.x;
            Ks[r * SPAD + dq + 1] = kv.y;
            Ks[r * SPAD + dq + 2] = kv.z;
            Ks[r * SPAD + dq + 3] = kv.w;
            float4 vv = *(const float4*)(V + g);
            Vs[r * SPAD + dq + 0] = vv.x;
            Vs[r * SPAD + dq + 1] = vv.y;
            Vs[r * SPAD + dq + 2] = vv.z;
            Vs[r * SPAD + dq + 3] = vv.w;
        }
        __syncthreads();

        // Scores: s[i][j] = Q[r0+i] . K[c0+j]
        float s[4][4];
        #pragma unroll
        for (int i = 0; i < 4; i++)
            #pragma unroll
            for (int j = 0; j < 4; j++) s[i][j] = 0.f;

        #pragma unroll 8
        for (int d = 0; d < HEAD_DIM; d++) {
            float a[4], kq[4];
            #pragma unroll
            for (int i = 0; i < 4; i++) a[i]  = Qs[(r0 + i) * SPAD + d];
            #pragma unroll
            for (int j = 0; j < 4; j++) kq[j] = Ks[(c0 + j) * SPAD + d];
            #pragma unroll
            for (int i = 0; i < 4; i++)
                #pragma unroll
                for (int j = 0; j < 4; j++)
                    s[i][j] = fmaf(a[i], kq[j], s[i][j]);
        }

        // Online softmax per row (reduce across the 16 tx lanes of each row)
        #pragma unroll
        for (int i = 0; i < 4; i++) {
            float mx = -1e30f;
            #pragma unroll
            for (int j = 0; j < 4; j++) {
                s[i][j] *= scale;
                mx = fmaxf(mx, s[i][j]);
            }
            #pragma unroll
            for (int off = 1; off < 16; off <<= 1)
                mx = fmaxf(mx, __shfl_xor_sync(0xffffffffu, mx, off));

            const float mnew = fmaxf(m_i[i], mx);
            const float corr = __expf(m_i[i] - mnew);
            m_i[i] = mnew;

            float rs = 0.f;
            #pragma unroll
            for (int j = 0; j < 4; j++) {
                float p = __expf(s[i][j] - mnew);
                Ps[(r0 + i) * SPAD + c0 + j] = p;
                rs += p;
            }
            #pragma unroll
            for (int off = 1; off < 16; off <<= 1)
                rs += __shfl_xor_sync(0xffffffffu, rs, off);

            l_i[i] = l_i[i] * corr + rs;
            #pragma unroll
            for (int j = 0; j < 4; j++) o[i][j] *= corr;
        }
        __syncthreads();   // all of Ps written

        // O += P @ V   (o dims = c0..c0+3)
        #pragma unroll 8
        for (int c = 0; c < 64; c++) {
            float p[4], v[4];
            #pragma unroll
            for (int i = 0; i < 4; i++) p[i] = Ps[(r0 + i) * SPAD + c];
            #pragma unroll
            for (int j = 0; j < 4; j++) v[j] = Vs[c * SPAD + c0 + j];
            #pragma unroll
            for (int i = 0; i < 4; i++)
                #pragma unroll
                for (int j = 0; j < 4; j++)
                    o[i][j] = fmaf(p[i], v[j], o[i][j]);
        }
    }

    // Normalize and write context
    #pragma unroll
    for (int i = 0; i < 4; i++) {
        const float inv = 1.0f / l_i[i];
        float4 ov;
        ov.x = o[i][0] * inv;
        ov.y = o[i][1] * inv;
        ov.z = o[i][2] * inv;
        ov.w = o[i][3] * inv;
        *(float4*)(O + base + (size_t)(q0 + r0 + i) * D_MODEL + c0) = ov;
    }
}

// ---------------------------------------------------------------------------
// Launch: Q/K/V projections -> attention -> output projection
// Inputs (metadata order): x1, x2, Wq, bq, Wk, bk, Wv, bv, Wo, bo
// ---------------------------------------------------------------------------
extern "C" void kernel_launch(void* const* d_in, const int* in_sizes, int n_in,
                              void* d_out, int out_size)
{
    (void)in_sizes; (void)n_in; (void)out_size;

    const float* x1 = (const float*)d_in[0];
    const float* x2 = (const float*)d_in[1];
    const float* Wq = (const float*)d_in[2];
    const float* bq = (const float*)d_in[3];
    const float* Wk = (const float*)d_in[4];
    const float* bk = (const float*)d_in[5];
    const float* Wv = (const float*)d_in[6];
    const float* bv = (const float*)d_in[7];
    const float* Wo = (const float*)d_in[8];
    const float* bo = (const float*)d_in[9];
    float* out = (float*)d_out;

    float *Qp, *Kp, *Vp, *Cp;
    cudaGetSymbolAddress((void**)&Qp, g_Q);
    cudaGetSymbolAddress((void**)&Kp, g_K);
    cudaGetSymbolAddress((void**)&Vp, g_V);
    cudaGetSymbolAddress((void**)&Cp, g_C);

    const int smem_bytes = 4 * 64 * SPAD * (int)sizeof(float);   // 66560
    cudaFuncSetAttribute(attn_kernel,
                         cudaFuncAttributeMaxDynamicSharedMemorySize, smem_bytes);

    dim3 gemm_grid(D_MODEL / 128, M_TOT / 128);   // (8, 32)

    gemm_bias_kernel<<<gemm_grid, 256>>>(x1, Wq, bq, Qp, M_TOT, D_MODEL, D_MODEL);
    gemm_bias_kernel<<<gemm_grid, 256>>>(x2, Wk, bk, Kp, M_TOT, D_MODEL, D_MODEL);
    gemm_bias_kernel<<<gemm_grid, 256>>>(x2, Wv, bv, Vp, M_TOT, D_MODEL, D_MODEL);

    dim3 attn_grid(SEQ / 64, NUM_HEADS, B_SZ);    // (32, 16, 2)
    attn_kernel<<<attn_grid, 256, smem_bytes>>>(Qp, Kp, Vp, Cp);

    gemm_bias_kernel<<<gemm_grid, 256>>>(Cp, Wo, bo, out, M_TOT, D_MODEL, D_MODEL);
}

// round 6
// speedup vs baseline: 1.3643x; 1.3643x over previous
#include <cuda_runtime.h>
#include <cstdint>
#include <cmath>

// Problem constants (fixed by the reference)
#define D_MODEL   1024
#define NUM_HEADS 16
#define HEAD_DIM  64
#define B_SZ      2
#define SEQ       2048
#define M_TOT     (B_SZ * SEQ)   // 4096 rows for all projection GEMMs

// Scratch (allocation-free rule: __device__ globals). 4 x 16 MB = 64 MB.
__device__ float g_Q[(size_t)M_TOT * D_MODEL];
__device__ float g_K[(size_t)M_TOT * D_MODEL];
__device__ float g_V[(size_t)M_TOT * D_MODEL];
__device__ float g_C[(size_t)M_TOT * D_MODEL];

// ---------------------------------------------------------------------------
// tf32 helpers
// ---------------------------------------------------------------------------
__device__ __forceinline__ float f2tf32(float x) {
    asm("cvt.rna.tf32.f32 %0, %0;" : "+f"(x));
    return x;
}

__device__ __forceinline__ void mma_tf32(float& c0, float& c1, float& c2, float& c3,
                                         float a0, float a1, float a2, float a3,
                                         float b0, float b1)
{
    asm volatile(
        "mma.sync.aligned.m16n8k8.row.col.f32.tf32.tf32.f32 "
        "{%0,%1,%2,%3}, {%4,%5,%6,%7}, {%8,%9}, {%0,%1,%2,%3};\n"
        : "+f"(c0), "+f"(c1), "+f"(c2), "+f"(c3)
        : "r"(__float_as_uint(a0)), "r"(__float_as_uint(a1)),
          "r"(__float_as_uint(a2)), "r"(__float_as_uint(a3)),
          "r"(__float_as_uint(b0)), "r"(__float_as_uint(b1)));
}

// ---------------------------------------------------------------------------
// GEMM + bias (tf32 tensor cores):  Y[M,N] = X[M,K] @ W[K,N] + b[N]
// CTA tile 128x128, BK=16, 256 threads = 8 warps in a 2(m) x 4(n) grid.
// Warp tile 64x32 = 4x4 grid of m16n8k8 mma tiles. Double-buffered smem.
// Smem pitch 136 floats (136 mod 32 == 8) makes every fragment LDS pattern
// hit bank 8*(lane%4) + (lane>>2) + const  -> conflict-free.
// ---------------------------------------------------------------------------
#define GPITCH 136

__global__ __launch_bounds__(256, 2) void gemm_tf32_kernel(
    const float* __restrict__ X, const float* __restrict__ W,
    const float* __restrict__ bias, float* __restrict__ Y,
    int M, int N, int K)
{
    __shared__ __align__(16) float As[2][16][GPITCH];   // As[buf][k][m]
    __shared__ __align__(16) float Bs[2][16][GPITCH];   // Bs[buf][k][n]

    const int tid  = threadIdx.x;
    const int lane = tid & 31;
    const int warp = tid >> 5;
    const int wm   = (warp >> 2) * 64;   // warp m offset inside CTA tile
    const int wn   = (warp & 3) * 32;    // warp n offset inside CTA tile
    const int r    = lane >> 2;          // fragment row group 0..7
    const int c    = lane & 3;           // fragment k group   0..3

    const int m0 = blockIdx.y * 128;
    const int n0 = blockIdx.x * 128;

    float acc[4][4][4];
    #pragma unroll
    for (int i = 0; i < 4; i++)
        #pragma unroll
        for (int j = 0; j < 4; j++)
            #pragma unroll
            for (int q = 0; q < 4; q++) acc[i][j][q] = 0.f;

    // gmem staging maps
    const int a_row = tid >> 1;          // 0..127
    const int a_kq  = (tid & 1) * 8;     // 0 or 8
    const int b_k   = tid >> 5;          // 0..7 (plus +8 second row)
    const int b_n4  = (tid & 31) * 4;    // 0..124

    const float* Xp = X + (size_t)(m0 + a_row) * K + a_kq;
    const float* Wp = W + (size_t)b_k * N + n0 + b_n4;

    float sa[8], sb[8];

    // prologue: load stage 0
    {
        float4 v0 = *(const float4*)(Xp + 0);
        float4 v1 = *(const float4*)(Xp + 4);
        sa[0]=v0.x; sa[1]=v0.y; sa[2]=v0.z; sa[3]=v0.w;
        sa[4]=v1.x; sa[5]=v1.y; sa[6]=v1.z; sa[7]=v1.w;
        float4 w0 = *(const float4*)(Wp);
        float4 w1 = *(const float4*)(Wp + (size_t)8 * N);
        sb[0]=w0.x; sb[1]=w0.y; sb[2]=w0.z; sb[3]=w0.w;
        sb[4]=w1.x; sb[5]=w1.y; sb[6]=w1.z; sb[7]=w1.w;
    }
    #pragma unroll
    for (int j = 0; j < 8; j++) As[0][a_kq + j][a_row] = f2tf32(sa[j]);
    {
        float4 t0 = make_float4(f2tf32(sb[0]), f2tf32(sb[1]), f2tf32(sb[2]), f2tf32(sb[3]));
        float4 t1 = make_float4(f2tf32(sb[4]), f2tf32(sb[5]), f2tf32(sb[6]), f2tf32(sb[7]));
        *(float4*)&Bs[0][b_k][b_n4]     = t0;
        *(float4*)&Bs[0][b_k + 8][b_n4] = t1;
    }
    __syncthreads();

    const int nIter = K / 16;
    for (int it = 0; it < nIter; it++) {
        const int buf = it & 1;

        // prefetch next stage into registers
        if (it + 1 < nIter) {
            const int k0 = (it + 1) * 16;
            float4 v0 = *(const float4*)(Xp + k0);
            float4 v1 = *(const float4*)(Xp + k0 + 4);
            sa[0]=v0.x; sa[1]=v0.y; sa[2]=v0.z; sa[3]=v0.w;
            sa[4]=v1.x; sa[5]=v1.y; sa[6]=v1.z; sa[7]=v1.w;
            float4 w0 = *(const float4*)(Wp + (size_t)k0 * N);
            float4 w1 = *(const float4*)(Wp + (size_t)(k0 + 8) * N);
            sb[0]=w0.x; sb[1]=w0.y; sb[2]=w0.z; sb[3]=w0.w;
            sb[4]=w1.x; sb[5]=w1.y; sb[6]=w1.z; sb[7]=w1.w;
        }

        // compute: 2 k-steps of 8
        #pragma unroll
        for (int s = 0; s < 2; s++) {
            const int kb = s * 8;
            float af[4][4], bf[4][2];
            #pragma unroll
            for (int mi = 0; mi < 4; mi++) {
                const int mb = wm + 16 * mi;
                af[mi][0] = As[buf][kb + c    ][mb + r    ];
                af[mi][1] = As[buf][kb + c    ][mb + r + 8];
                af[mi][2] = As[buf][kb + c + 4][mb + r    ];
                af[mi][3] = As[buf][kb + c + 4][mb + r + 8];
            }
            #pragma unroll
            for (int ni = 0; ni < 4; ni++) {
                const int nb = wn + 8 * ni;
                bf[ni][0] = Bs[buf][kb + c    ][nb + r];
                bf[ni][1] = Bs[buf][kb + c + 4][nb + r];
            }
            #pragma unroll
            for (int mi = 0; mi < 4; mi++)
                #pragma unroll
                for (int ni = 0; ni < 4; ni++)
                    mma_tf32(acc[mi][ni][0], acc[mi][ni][1], acc[mi][ni][2], acc[mi][ni][3],
                             af[mi][0], af[mi][1], af[mi][2], af[mi][3],
                             bf[ni][0], bf[ni][1]);
        }

        // store next stage
        if (it + 1 < nIter) {
            const int nb = (it + 1) & 1;
            #pragma unroll
            for (int j = 0; j < 8; j++) As[nb][a_kq + j][a_row] = f2tf32(sa[j]);
            float4 t0 = make_float4(f2tf32(sb[0]), f2tf32(sb[1]), f2tf32(sb[2]), f2tf32(sb[3]));
            float4 t1 = make_float4(f2tf32(sb[4]), f2tf32(sb[5]), f2tf32(sb[6]), f2tf32(sb[7]));
            *(float4*)&Bs[nb][b_k][b_n4]     = t0;
            *(float4*)&Bs[nb][b_k + 8][b_n4] = t1;
        }
        __syncthreads();
    }

    // epilogue: add bias, write. c-frag layout: rows r, r+8; cols 2c, 2c+1.
    #pragma unroll
    for (int mi = 0; mi < 4; mi++) {
        const int m = m0 + wm + 16 * mi + r;
        #pragma unroll
        for (int ni = 0; ni < 4; ni++) {
            const int n = n0 + wn + 8 * ni + 2 * c;
            const float bx = bias[n], by = bias[n + 1];
            float2 o0 = make_float2(acc[mi][ni][0] + bx, acc[mi][ni][1] + by);
            float2 o1 = make_float2(acc[mi][ni][2] + bx, acc[mi][ni][3] + by);
            *(float2*)(Y + (size_t)m * N + n)       = o0;
            *(float2*)(Y + (size_t)(m + 8) * N + n) = o1;
        }
    }
}

// ---------------------------------------------------------------------------
// Flash attention (fp32). One CTA = one (batch, head, 64-row Q tile).
// (unchanged from R3 — converted to tensor cores next round)
// ---------------------------------------------------------------------------
#define SPAD 65   // smem row pitch (floats)

__global__ __launch_bounds__(256) void attn_kernel(
    const float* __restrict__ Q, const float* __restrict__ K,
    const float* __restrict__ V, float* __restrict__ O)
{
    extern __shared__ float sm[];
    float* Qs = sm;                 // [64][SPAD]
    float* Ks = Qs + 64 * SPAD;
    float* Vs = Ks + 64 * SPAD;
    float* Ps = Vs + 64 * SPAD;

    const int tid = threadIdx.x;
    const int tx  = tid & 15;
    const int ty  = tid >> 4;
    const int qt  = blockIdx.x;   // 0..31
    const int h   = blockIdx.y;   // 0..15
    const int b   = blockIdx.z;   // 0..1
    const int q0  = qt * 64;
    const size_t base = (size_t)b * SEQ * D_MODEL + (size_t)h * HEAD_DIM;

    #pragma unroll
    for (int i = 0; i < 4; i++) {
        const int idx = i * 256 + tid;
        const int rr  = idx >> 4;
        const int dq  = (idx & 15) * 4;
        float4 v = *(const float4*)(Q + base + (size_t)(q0 + rr) * D_MODEL + dq);
        Qs[rr * SPAD + dq + 0] = v.x;
        Qs[rr * SPAD + dq + 1] = v.y;
        Qs[rr * SPAD + dq + 2] = v.z;
        Qs[rr * SPAD + dq + 3] = v.w;
    }

    float m_i[4], l_i[4], o[4][4];
    #pragma unroll
    for (int i = 0; i < 4; i++) {
        m_i[i] = -1e30f;
        l_i[i] = 0.f;
        #pragma unroll
        for (int j = 0; j < 4; j++) o[i][j] = 0.f;
    }

    const int r0 = ty * 4;
    const int c0 = tx * 4;
    const float scale = 0.125f;

    for (int kt = 0; kt < SEQ / 64; kt++) {
        __syncthreads();

        #pragma unroll
        for (int i = 0; i < 4; i++) {
            const int idx = i * 256 + tid;
            const int rr  = idx >> 4;
            const int dq  = (idx & 15) * 4;
            const size_t g = base + (size_t)(kt * 64 + rr) * D_MODEL + dq;
            float4 kv = *(const float4*)(K + g);
            Ks[rr * SPAD + dq + 0] = kv.x;
            Ks[rr * SPAD + dq + 1] = kv.y;
            Ks[rr * SPAD + dq + 2] = kv.z;
            Ks[rr * SPAD + dq + 3] = kv.w;
            float4 vv = *(const float4*)(V + g);
            Vs[rr * SPAD + dq + 0] = vv.x;
            Vs[rr * SPAD + dq + 1] = vv.y;
            Vs[rr * SPAD + dq + 2] = vv.z;
            Vs[rr * SPAD + dq + 3] = vv.w;
        }
        __syncthreads();

        float s[4][4];
        #pragma unroll
        for (int i = 0; i < 4; i++)
            #pragma unroll
            for (int j = 0; j < 4; j++) s[i][j] = 0.f;

        #pragma unroll 8
        for (int d = 0; d < HEAD_DIM; d++) {
            float a[4], kq[4];
            #pragma unroll
            for (int i = 0; i < 4; i++) a[i]  = Qs[(r0 + i) * SPAD + d];
            #pragma unroll
            for (int j = 0; j < 4; j++) kq[j] = Ks[(c0 + j) * SPAD + d];
            #pragma unroll
            for (int i = 0; i < 4; i++)
                #pragma unroll
                for (int j = 0; j < 4; j++)
                    s[i][j] = fmaf(a[i], kq[j], s[i][j]);
        }

        #pragma unroll
        for (int i = 0; i < 4; i++) {
            float mx = -1e30f;
            #pragma unroll
            for (int j = 0; j < 4; j++) {
                s[i][j] *= scale;
                mx = fmaxf(mx, s[i][j]);
            }
            #pragma unroll
            for (int off = 1; off < 16; off <<= 1)
                mx = fmaxf(mx, __shfl_xor_sync(0xffffffffu, mx, off));

            const float mnew = fmaxf(m_i[i], mx);
            const float corr = __expf(m_i[i] - mnew);
            m_i[i] = mnew;

            float rs = 0.f;
            #pragma unroll
            for (int j = 0; j < 4; j++) {
                float p = __expf(s[i][j] - mnew);
                Ps[(r0 + i) * SPAD + c0 + j] = p;
                rs += p;
            }
            #pragma unroll
            for (int off = 1; off < 16; off <<= 1)
                rs += __shfl_xor_sync(0xffffffffu, rs, off);

            l_i[i] = l_i[i] * corr + rs;
            #pragma unroll
            for (int j = 0; j < 4; j++) o[i][j] *= corr;
        }
        __syncthreads();

        #pragma unroll 8
        for (int cc = 0; cc < 64; cc++) {
            float p[4], v[4];
            #pragma unroll
            for (int i = 0; i < 4; i++) p[i] = Ps[(r0 + i) * SPAD + cc];
            #pragma unroll
            for (int j = 0; j < 4; j++) v[j] = Vs[cc * SPAD + c0 + j];
            #pragma unroll
            for (int i = 0; i < 4; i++)
                #pragma unroll
                for (int j = 0; j < 4; j++)
                    o[i][j] = fmaf(p[i], v[j], o[i][j]);
        }
    }

    #pragma unroll
    for (int i = 0; i < 4; i++) {
        const float inv = 1.0f / l_i[i];
        float4 ov;
        ov.x = o[i][0] * inv;
        ov.y = o[i][1] * inv;
        ov.z = o[i][2] * inv;
        ov.w = o[i][3] * inv;
        *(float4*)(O + base + (size_t)(q0 + r0 + i) * D_MODEL + c0) = ov;
    }
}

// ---------------------------------------------------------------------------
// Launch: Q/K/V projections -> attention -> output projection
// Inputs (metadata order): x1, x2, Wq, bq, Wk, bk, Wv, bv, Wo, bo
// ---------------------------------------------------------------------------
extern "C" void kernel_launch(void* const* d_in, const int* in_sizes, int n_in,
                              void* d_out, int out_size)
{
    (void)in_sizes; (void)n_in; (void)out_size;

    const float* x1 = (const float*)d_in[0];
    const float* x2 = (const float*)d_in[1];
    const float* Wq = (const float*)d_in[2];
    const float* bq = (const float*)d_in[3];
    const float* Wk = (const float*)d_in[4];
    const float* bk = (const float*)d_in[5];
    const float* Wv = (const float*)d_in[6];
    const float* bv = (const float*)d_in[7];
    const float* Wo = (const float*)d_in[8];
    const float* bo = (const float*)d_in[9];
    float* out = (float*)d_out;

    float *Qp, *Kp, *Vp, *Cp;
    cudaGetSymbolAddress((void**)&Qp, g_Q);
    cudaGetSymbolAddress((void**)&Kp, g_K);
    cudaGetSymbolAddress((void**)&Vp, g_V);
    cudaGetSymbolAddress((void**)&Cp, g_C);

    const int smem_bytes = 4 * 64 * SPAD * (int)sizeof(float);   // 66560
    cudaFuncSetAttribute(attn_kernel,
                         cudaFuncAttributeMaxDynamicSharedMemorySize, smem_bytes);

    dim3 gemm_grid(D_MODEL / 128, M_TOT / 128);   // (8, 32)

    gemm_tf32_kernel<<<gemm_grid, 256>>>(x1, Wq, bq, Qp, M_TOT, D_MODEL, D_MODEL);
    gemm_tf32_kernel<<<gemm_grid, 256>>>(x2, Wk, bk, Kp, M_TOT, D_MODEL, D_MODEL);
    gemm_tf32_kernel<<<gemm_grid, 256>>>(x2, Wv, bv, Vp, M_TOT, D_MODEL, D_MODEL);

    dim3 attn_grid(SEQ / 64, NUM_HEADS, B_SZ);    // (32, 16, 2)
    attn_kernel<<<attn_grid, 256, smem_bytes>>>(Qp, Kp, Vp, Cp);

    gemm_tf32_kernel<<<gemm_grid, 256>>>(Cp, Wo, bo, out, M_TOT, D_MODEL, D_MODEL);
}

// round 7
// speedup vs baseline: 2.9321x; 2.1492x over previous
#include <cuda_runtime.h>
#include <cstdint>
#include <cmath>

// Problem constants (fixed by the reference)
#define D_MODEL   1024
#define NUM_HEADS 16
#define HEAD_DIM  64
#define B_SZ      2
#define SEQ       2048
#define M_TOT     (B_SZ * SEQ)   // 4096 rows for all projection GEMMs

// Scratch (allocation-free rule: __device__ globals). 4 x 16 MB = 64 MB.
__device__ float g_Q[(size_t)M_TOT * D_MODEL];
__device__ float g_K[(size_t)M_TOT * D_MODEL];
__device__ float g_V[(size_t)M_TOT * D_MODEL];
__device__ float g_C[(size_t)M_TOT * D_MODEL];

// ---------------------------------------------------------------------------
// tf32 helpers
// ---------------------------------------------------------------------------
__device__ __forceinline__ float f2tf32(float x) {
    asm("cvt.rna.tf32.f32 %0, %0;" : "+f"(x));
    return x;
}

__device__ __forceinline__ void mma_tf32(float& c0, float& c1, float& c2, float& c3,
                                         float a0, float a1, float a2, float a3,
                                         float b0, float b1)
{
    asm volatile(
        "mma.sync.aligned.m16n8k8.row.col.f32.tf32.tf32.f32 "
        "{%0,%1,%2,%3}, {%4,%5,%6,%7}, {%8,%9}, {%0,%1,%2,%3};\n"
        : "+f"(c0), "+f"(c1), "+f"(c2), "+f"(c3)
        : "r"(__float_as_uint(a0)), "r"(__float_as_uint(a1)),
          "r"(__float_as_uint(a2)), "r"(__float_as_uint(a3)),
          "r"(__float_as_uint(b0)), "r"(__float_as_uint(b1)));
}

// ---------------------------------------------------------------------------
// GEMM + bias (tf32 tensor cores):  Y[M,N] = X[M,K] @ W[K,N] + b[N]
// (unchanged from R5 — proven at 1414us)
// ---------------------------------------------------------------------------
#define GPITCH 136

__global__ __launch_bounds__(256, 2) void gemm_tf32_kernel(
    const float* __restrict__ X, const float* __restrict__ W,
    const float* __restrict__ bias, float* __restrict__ Y,
    int M, int N, int K)
{
    __shared__ __align__(16) float As[2][16][GPITCH];   // As[buf][k][m]
    __shared__ __align__(16) float Bs[2][16][GPITCH];   // Bs[buf][k][n]

    const int tid  = threadIdx.x;
    const int lane = tid & 31;
    const int warp = tid >> 5;
    const int wm   = (warp >> 2) * 64;
    const int wn   = (warp & 3) * 32;
    const int r    = lane >> 2;
    const int c    = lane & 3;

    const int m0 = blockIdx.y * 128;
    const int n0 = blockIdx.x * 128;

    float acc[4][4][4];
    #pragma unroll
    for (int i = 0; i < 4; i++)
        #pragma unroll
        for (int j = 0; j < 4; j++)
            #pragma unroll
            for (int q = 0; q < 4; q++) acc[i][j][q] = 0.f;

    const int a_row = tid >> 1;
    const int a_kq  = (tid & 1) * 8;
    const int b_k   = tid >> 5;
    const int b_n4  = (tid & 31) * 4;

    const float* Xp = X + (size_t)(m0 + a_row) * K + a_kq;
    const float* Wp = W + (size_t)b_k * N + n0 + b_n4;

    float sa[8], sb[8];

    {
        float4 v0 = *(const float4*)(Xp + 0);
        float4 v1 = *(const float4*)(Xp + 4);
        sa[0]=v0.x; sa[1]=v0.y; sa[2]=v0.z; sa[3]=v0.w;
        sa[4]=v1.x; sa[5]=v1.y; sa[6]=v1.z; sa[7]=v1.w;
        float4 w0 = *(const float4*)(Wp);
        float4 w1 = *(const float4*)(Wp + (size_t)8 * N);
        sb[0]=w0.x; sb[1]=w0.y; sb[2]=w0.z; sb[3]=w0.w;
        sb[4]=w1.x; sb[5]=w1.y; sb[6]=w1.z; sb[7]=w1.w;
    }
    #pragma unroll
    for (int j = 0; j < 8; j++) As[0][a_kq + j][a_row] = f2tf32(sa[j]);
    {
        float4 t0 = make_float4(f2tf32(sb[0]), f2tf32(sb[1]), f2tf32(sb[2]), f2tf32(sb[3]));
        float4 t1 = make_float4(f2tf32(sb[4]), f2tf32(sb[5]), f2tf32(sb[6]), f2tf32(sb[7]));
        *(float4*)&Bs[0][b_k][b_n4]     = t0;
        *(float4*)&Bs[0][b_k + 8][b_n4] = t1;
    }
    __syncthreads();

    const int nIter = K / 16;
    for (int it = 0; it < nIter; it++) {
        const int buf = it & 1;

        if (it + 1 < nIter) {
            const int k0 = (it + 1) * 16;
            float4 v0 = *(const float4*)(Xp + k0);
            float4 v1 = *(const float4*)(Xp + k0 + 4);
            sa[0]=v0.x; sa[1]=v0.y; sa[2]=v0.z; sa[3]=v0.w;
            sa[4]=v1.x; sa[5]=v1.y; sa[6]=v1.z; sa[7]=v1.w;
            float4 w0 = *(const float4*)(Wp + (size_t)k0 * N);
            float4 w1 = *(const float4*)(Wp + (size_t)(k0 + 8) * N);
            sb[0]=w0.x; sb[1]=w0.y; sb[2]=w0.z; sb[3]=w0.w;
            sb[4]=w1.x; sb[5]=w1.y; sb[6]=w1.z; sb[7]=w1.w;
        }

        #pragma unroll
        for (int s = 0; s < 2; s++) {
            const int kb = s * 8;
            float af[4][4], bf[4][2];
            #pragma unroll
            for (int mi = 0; mi < 4; mi++) {
                const int mb = wm + 16 * mi;
                af[mi][0] = As[buf][kb + c    ][mb + r    ];
                af[mi][1] = As[buf][kb + c    ][mb + r + 8];
                af[mi][2] = As[buf][kb + c + 4][mb + r    ];
                af[mi][3] = As[buf][kb + c + 4][mb + r + 8];
            }
            #pragma unroll
            for (int ni = 0; ni < 4; ni++) {
                const int nb = wn + 8 * ni;
                bf[ni][0] = Bs[buf][kb + c    ][nb + r];
                bf[ni][1] = Bs[buf][kb + c + 4][nb + r];
            }
            #pragma unroll
            for (int mi = 0; mi < 4; mi++)
                #pragma unroll
                for (int ni = 0; ni < 4; ni++)
                    mma_tf32(acc[mi][ni][0], acc[mi][ni][1], acc[mi][ni][2], acc[mi][ni][3],
                             af[mi][0], af[mi][1], af[mi][2], af[mi][3],
                             bf[ni][0], bf[ni][1]);
        }

        if (it + 1 < nIter) {
            const int nb = (it + 1) & 1;
            #pragma unroll
            for (int j = 0; j < 8; j++) As[nb][a_kq + j][a_row] = f2tf32(sa[j]);
            float4 t0 = make_float4(f2tf32(sb[0]), f2tf32(sb[1]), f2tf32(sb[2]), f2tf32(sb[3]));
            float4 t1 = make_float4(f2tf32(sb[4]), f2tf32(sb[5]), f2tf32(sb[6]), f2tf32(sb[7]));
            *(float4*)&Bs[nb][b_k][b_n4]     = t0;
            *(float4*)&Bs[nb][b_k + 8][b_n4] = t1;
        }
        __syncthreads();
    }

    #pragma unroll
    for (int mi = 0; mi < 4; mi++) {
        const int m = m0 + wm + 16 * mi + r;
        #pragma unroll
        for (int ni = 0; ni < 4; ni++) {
            const int n = n0 + wn + 8 * ni + 2 * c;
            const float bx = bias[n], by = bias[n + 1];
            float2 o0 = make_float2(acc[mi][ni][0] + bx, acc[mi][ni][1] + by);
            float2 o1 = make_float2(acc[mi][ni][2] + bx, acc[mi][ni][3] + by);
            *(float2*)(Y + (size_t)m * N + n)       = o0;
            *(float2*)(Y + (size_t)(m + 8) * N + n) = o1;
        }
    }
}

// ---------------------------------------------------------------------------
// Flash attention with tf32 tensor cores.
// CTA = (b, h, 128-row Q tile). 256 threads = 8 warps; warp w owns Q rows
// [w*16, w*16+16). K processed in tiles of 64.
//
// S = Q·K^T via m16n8k8 (A=Q row-major over d, B=K "col" layout: b = K[n][k]).
// Softmax on S accumulator fragments in registers (fp32), row reductions via
// shfl over the 4 lanes holding each row. P staged through per-warp-private
// smem rows (syncwarp only) to become the A operand of P·V.
// For P·V, B[k=seq][n=d] = V[seq][d] -> V needs NO transpose.
//
// Bank-conflict-free pitches:
//   Q/K/P pitch 68 (=4 mod 32): frag address bank = 4r+c  (bijective, r<8,c<4)
//   V     pitch 72 (=8 mod 32): frag address bank = 8c+r  (bijective)
// ---------------------------------------------------------------------------
#define QT      128
#define KTILE   64
#define KP      68
#define VP      72

__global__ __launch_bounds__(256, 2) void attn_mma_kernel(
    const float* __restrict__ Q, const float* __restrict__ K,
    const float* __restrict__ V, float* __restrict__ O)
{
    extern __shared__ float sm[];
    float* Qs = sm;                       // [128][KP]
    float* Ps = Qs + QT * KP;             // [128][KP]
    float* Ks = Ps + QT * KP;             // [64][KP]
    float* Vs = Ks + KTILE * KP;          // [64][VP]

    const int tid  = threadIdx.x;
    const int lane = tid & 31;
    const int warp = tid >> 5;
    const int r    = lane >> 2;   // fragment row group 0..7
    const int c    = lane & 3;    // fragment k/col group 0..3
    const int wq   = warp * 16;   // warp's Q-row strip

    const int q0 = blockIdx.x * QT;
    const int h  = blockIdx.y;
    const int b  = blockIdx.z;
    const size_t base = (size_t)b * SEQ * D_MODEL + (size_t)h * HEAD_DIM;

    // ---- load Q tile (128 x 64) -> Qs (tf32) ----
    #pragma unroll
    for (int i = 0; i < 8; i++) {
        const int idx  = i * 256 + tid;       // 2048 float4 slots
        const int row  = idx >> 4;            // 0..127
        const int col4 = (idx & 15) * 4;      // 0..60
        float4 v = *(const float4*)(Q + base + (size_t)(q0 + row) * D_MODEL + col4);
        Qs[row * KP + col4 + 0] = f2tf32(v.x);
        Qs[row * KP + col4 + 1] = f2tf32(v.y);
        Qs[row * KP + col4 + 2] = f2tf32(v.z);
        Qs[row * KP + col4 + 3] = f2tf32(v.w);
    }

    float oacc[8][4];
    #pragma unroll
    for (int i = 0; i < 8; i++)
        #pragma unroll
        for (int j = 0; j < 4; j++) oacc[i][j] = 0.f;
    float m0v = -1e30f, m1v = -1e30f, l0 = 0.f, l1 = 0.f;

    const float scale = 0.125f;   // 1/sqrt(64)

    for (int kt = 0; kt < SEQ / KTILE; kt++) {
        __syncthreads();   // previous iteration's consumers of Ks/Vs done

        // ---- load K,V tiles (64 x 64 each) -> smem (tf32) ----
        #pragma unroll
        for (int i = 0; i < 4; i++) {
            const int idx  = i * 256 + tid;       // 1024 float4 slots
            const int row  = idx >> 4;            // 0..63
            const int col4 = (idx & 15) * 4;
            const size_t g = base + (size_t)(kt * KTILE + row) * D_MODEL + col4;
            float4 kv = *(const float4*)(K + g);
            Ks[row * KP + col4 + 0] = f2tf32(kv.x);
            Ks[row * KP + col4 + 1] = f2tf32(kv.y);
            Ks[row * KP + col4 + 2] = f2tf32(kv.z);
            Ks[row * KP + col4 + 3] = f2tf32(kv.w);
            float4 vv = *(const float4*)(V + g);
            Vs[row * VP + col4 + 0] = f2tf32(vv.x);
            Vs[row * VP + col4 + 1] = f2tf32(vv.y);
            Vs[row * VP + col4 + 2] = f2tf32(vv.z);
            Vs[row * VP + col4 + 3] = f2tf32(vv.w);
        }
        __syncthreads();

        // ---- S = Q·K^T : 16 x 64 per warp, 8 n-tiles x 8 k-steps ----
        float sacc[8][4];
        #pragma unroll
        for (int i = 0; i < 8; i++)
            #pragma unroll
            for (int j = 0; j < 4; j++) sacc[i][j] = 0.f;

        #pragma unroll
        for (int kk = 0; kk < 8; kk++) {
            const int kb = kk * 8;
            float a0 = Qs[(wq + r    ) * KP + kb + c    ];
            float a1 = Qs[(wq + r + 8) * KP + kb + c    ];
            float a2 = Qs[(wq + r    ) * KP + kb + c + 4];
            float a3 = Qs[(wq + r + 8) * KP + kb + c + 4];
            #pragma unroll
            for (int nt = 0; nt < 8; nt++) {
                float b0 = Ks[(nt * 8 + r) * KP + kb + c    ];
                float b1 = Ks[(nt * 8 + r) * KP + kb + c + 4];
                mma_tf32(sacc[nt][0], sacc[nt][1], sacc[nt][2], sacc[nt][3],
                         a0, a1, a2, a3, b0, b1);
            }
        }

        // ---- online softmax on fragments (rows r and r+8) ----
        float mx0 = -1e30f, mx1 = -1e30f;
        #pragma unroll
        for (int nt = 0; nt < 8; nt++) {
            sacc[nt][0] *= scale; sacc[nt][1] *= scale;
            sacc[nt][2] *= scale; sacc[nt][3] *= scale;
            mx0 = fmaxf(mx0, fmaxf(sacc[nt][0], sacc[nt][1]));
            mx1 = fmaxf(mx1, fmaxf(sacc[nt][2], sacc[nt][3]));
        }
        mx0 = fmaxf(mx0, __shfl_xor_sync(0xffffffffu, mx0, 1));
        mx0 = fmaxf(mx0, __shfl_xor_sync(0xffffffffu, mx0, 2));
        mx1 = fmaxf(mx1, __shfl_xor_sync(0xffffffffu, mx1, 1));
        mx1 = fmaxf(mx1, __shfl_xor_sync(0xffffffffu, mx1, 2));

        const float mn0 = fmaxf(m0v, mx0);
        const float mn1 = fmaxf(m1v, mx1);
        const float corr0 = __expf(m0v - mn0);
        const float corr1 = __expf(m1v - mn1);
        m0v = mn0; m1v = mn1;

        float rs0 = 0.f, rs1 = 0.f;
        #pragma unroll
        for (int nt = 0; nt < 8; nt++) {
            sacc[nt][0] = __expf(sacc[nt][0] - mn0);
            sacc[nt][1] = __expf(sacc[nt][1] - mn0);
            sacc[nt][2] = __expf(sacc[nt][2] - mn1);
            sacc[nt][3] = __expf(sacc[nt][3] - mn1);
            rs0 += sacc[nt][0] + sacc[nt][1];
            rs1 += sacc[nt][2] + sacc[nt][3];
        }
        rs0 += __shfl_xor_sync(0xffffffffu, rs0, 1);
        rs0 += __shfl_xor_sync(0xffffffffu, rs0, 2);
        rs1 += __shfl_xor_sync(0xffffffffu, rs1, 1);
        rs1 += __shfl_xor_sync(0xffffffffu, rs1, 2);

        l0 = l0 * corr0 + rs0;
        l1 = l1 * corr1 + rs1;
        #pragma unroll
        for (int nt = 0; nt < 8; nt++) {
            oacc[nt][0] *= corr0; oacc[nt][1] *= corr0;
            oacc[nt][2] *= corr1; oacc[nt][3] *= corr1;
        }

        // ---- write P to per-warp-private smem rows (accumulator layout) ----
        #pragma unroll
        for (int nt = 0; nt < 8; nt++) {
            float2 p0 = make_float2(f2tf32(sacc[nt][0]), f2tf32(sacc[nt][1]));
            float2 p1 = make_float2(f2tf32(sacc[nt][2]), f2tf32(sacc[nt][3]));
            *(float2*)&Ps[(wq + r    ) * KP + nt * 8 + 2 * c] = p0;
            *(float2*)&Ps[(wq + r + 8) * KP + nt * 8 + 2 * c] = p1;
        }
        __syncwarp();   // P rows are warp-private; warp-level ordering suffices

        // ---- O += P·V : 16 x 64 per warp, 8 d-tiles x 8 k-steps over seq ----
        #pragma unroll
        for (int kk = 0; kk < 8; kk++) {
            const int kb = kk * 8;
            float a0 = Ps[(wq + r    ) * KP + kb + c    ];
            float a1 = Ps[(wq + r + 8) * KP + kb + c    ];
            float a2 = Ps[(wq + r    ) * KP + kb + c + 4];
            float a3 = Ps[(wq + r + 8) * KP + kb + c + 4];
            #pragma unroll
            for (int nt = 0; nt < 8; nt++) {
                float b0 = Vs[(kb + c    ) * VP + nt * 8 + r];
                float b1 = Vs[(kb + c + 4) * VP + nt * 8 + r];
                mma_tf32(oacc[nt][0], oacc[nt][1], oacc[nt][2], oacc[nt][3],
                         a0, a1, a2, a3, b0, b1);
            }
        }
    }

    // ---- normalize and write context ----
    const float inv0 = 1.0f / l0;
    const float inv1 = 1.0f / l1;
    #pragma unroll
    for (int nt = 0; nt < 8; nt++) {
        const int col = nt * 8 + 2 * c;
        float2 o0 = make_float2(oacc[nt][0] * inv0, oacc[nt][1] * inv0);
        float2 o1 = make_float2(oacc[nt][2] * inv1, oacc[nt][3] * inv1);
        *(float2*)(O + base + (size_t)(q0 + wq + r    ) * D_MODEL + col) = o0;
        *(float2*)(O + base + (size_t)(q0 + wq + r + 8) * D_MODEL + col) = o1;
    }
}

// ---------------------------------------------------------------------------
// Launch: Q/K/V projections -> attention -> output projection
// Inputs (metadata order): x1, x2, Wq, bq, Wk, bk, Wv, bv, Wo, bo
// ---------------------------------------------------------------------------
extern "C" void kernel_launch(void* const* d_in, const int* in_sizes, int n_in,
                              void* d_out, int out_size)
{
    (void)in_sizes; (void)n_in; (void)out_size;

    const float* x1 = (const float*)d_in[0];
    const float* x2 = (const float*)d_in[1];
    const float* Wq = (const float*)d_in[2];
    const float* bq = (const float*)d_in[3];
    const float* Wk = (const float*)d_in[4];
    const float* bk = (const float*)d_in[5];
    const float* Wv = (const float*)d_in[6];
    const float* bv = (const float*)d_in[7];
    const float* Wo = (const float*)d_in[8];
    const float* bo = (const float*)d_in[9];
    float* out = (float*)d_out;

    float *Qp, *Kp, *Vp, *Cp;
    cudaGetSymbolAddress((void**)&Qp, g_Q);
    cudaGetSymbolAddress((void**)&Kp, g_K);
    cudaGetSymbolAddress((void**)&Vp, g_V);
    cudaGetSymbolAddress((void**)&Cp, g_C);

    const int attn_smem = (QT * KP + QT * KP + KTILE * KP + KTILE * VP) * (int)sizeof(float);
    cudaFuncSetAttribute(attn_mma_kernel,
                         cudaFuncAttributeMaxDynamicSharedMemorySize, attn_smem);

    dim3 gemm_grid(D_MODEL / 128, M_TOT / 128);   // (8, 32)

    gemm_tf32_kernel<<<gemm_grid, 256>>>(x1, Wq, bq, Qp, M_TOT, D_MODEL, D_MODEL);
    gemm_tf32_kernel<<<gemm_grid, 256>>>(x2, Wk, bk, Kp, M_TOT, D_MODEL, D_MODEL);
    gemm_tf32_kernel<<<gemm_grid, 256>>>(x2, Wv, bv, Vp, M_TOT, D_MODEL, D_MODEL);

    dim3 attn_grid(SEQ / QT, NUM_HEADS, B_SZ);    // (16, 16, 2)
    attn_mma_kernel<<<attn_grid, 256, attn_smem>>>(Qp, Kp, Vp, Cp);

    gemm_tf32_kernel<<<gemm_grid, 256>>>(Cp, Wo, bo, out, M_TOT, D_MODEL, D_MODEL);
}